// round 14
// baseline (speedup 1.0000x reference)
#include <cuda_runtime.h>
#include <cuda_bf16.h>
#include <cstdint>

// Problem constants
#define Bb 16
#define Ss 2048
#define Dd 1024
#define Vv 128          // vocab
#define Ll 4
#define NB (Dd/2)       // rotation blocks = 512
#define ROWS (Bb*Ss)    // 32768
#define DD2 (Dd*Dd)     // 1048576

// Tiled operand layout: [blk128][kslab32][digit2][row128][k32] bytes.
#define CELL   8192
#define BLKSZ  (32 * CELL)          // 256 KB per 128-row block (full K)
#define WSLOT  (8 * BLKSZ)          // 2 MB per DxD weight slot

// ---------------- scratch (device globals; no allocation allowed) ----------
__device__ float g_a [ROWS*Dd];          // residual stream
__device__ float g_uv[(size_t)ROWS*2*Dd];// combined u|v  [row][2048]
__device__ float g_w [ROWS*Dd];          // gate / relu out (fp32, pre-quant)
__device__ __align__(128) int8_t g_qa[(size_t)ROWS*Dd*2];           // tiled activations
__device__ float  g_sa [ROWS];           // activation row scales
// slots: 2l=Wx_l, 2l+1=Wv_l (l=0..3), 8+l=Wh_l, 12=Wo1, 13=Wo2
__device__ __align__(128) int8_t g_wq[(size_t)13*WSLOT + 2*BLKSZ];
__device__ float  g_sw [14*Dd];          // weight col scales (slot-major)
__device__ float  g_bc [Ll*2*Dd];        // concat biases [l][bx|bv]

__device__ __forceinline__ int clampi(int x, int lo, int hi) {
    return x < lo ? lo : (x > hi ? hi : x);
}
__device__ __forceinline__ uint32_t sw_off(int r, int c16) {
    return (uint32_t)(r * 32 + ((c16 ^ ((r >> 2) & 1)) << 4));
}

// ---------------- embedding gather ----------------
__global__ __launch_bounds__(256) void embed_kernel(const int* __restrict__ idx,
                                                    const float* __restrict__ emb,
                                                    float* __restrict__ a) {
    int i = blockIdx.x * 256 + threadIdx.x;
    int row = i >> 8;
    int col = i & 255;
    int tok = idx[row];
    ((float4*)a)[i] = ((const float4*)emb)[tok * 256 + col];
}

// ---------------- weight transpose + 2-digit int8 quant (tiled out) -------
#define WQ_STRIDE 1040
__global__ __launch_bounds__(256) void wquant_kernel(
        const float* __restrict__ Wx, const float* __restrict__ Wv,
        const float* __restrict__ Wh, const float* __restrict__ Wo1,
        const float* __restrict__ Wo2,
        const float* __restrict__ bxv, const float* __restrict__ bvv,
        int8_t* __restrict__ wq, float* __restrict__ sw,
        float* __restrict__ bc) {
    extern __shared__ char wsm[];
    char*  q1s  = wsm;
    char*  q2s  = wsm + 32 * WQ_STRIDE;
    float* part = (float*)(wsm + 64 * WQ_STRIDE);
    float* cmax = part + 8 * 32;

    int slot = blockIdx.y;
    const float* W;
    int Ndim = Dd;
    if (slot < 8)        W = ((slot & 1) ? Wv : Wx) + (size_t)(slot >> 1) * DD2;
    else if (slot < 12)  W = Wh + (size_t)(slot - 8) * DD2;
    else if (slot == 12) W = Wo1;
    else { W = Wo2; Ndim = Vv; }

    int t = threadIdx.x;
    if (slot < 8 && blockIdx.x == 0) {
        int l = slot >> 1;
        const float* src = ((slot & 1) ? bvv : bxv) + (size_t)l * Dd;
        float* dst = bc + (size_t)l * 2 * Dd + (slot & 1) * Dd;
        for (int i = t; i < Dd; i += 256) dst[i] = src[i];
    }

    int n0 = blockIdx.x * 32;
    if (n0 >= Ndim) return;
    int tc = t & 31, tr = t >> 5;

    float m = 0.f;
    for (int k = tr; k < Dd; k += 8)
        m = fmaxf(m, fabsf(W[(size_t)k * Ndim + n0 + tc]));
    part[tr * 32 + tc] = m;
    __syncthreads();
    if (t < 32) {
        float mm = part[t];
        #pragma unroll
        for (int r = 1; r < 8; r++) mm = fmaxf(mm, part[r * 32 + t]);
        mm = fmaxf(mm, 1e-30f);
        cmax[t] = mm;
        sw[slot * Dd + n0 + t] = mm * (1.0f / 127.0f);
    }
    __syncthreads();

    float inv = 127.0f / cmax[tc];
    for (int k = tr; k < Dd; k += 8) {
        float x = W[(size_t)k * Ndim + n0 + tc] * inv;
        int q1 = __float2int_rn(x);
        float r = x - (float)q1;
        int q2 = clampi(__float2int_rn(r * 256.0f), -127, 127);
        q1s[tc * WQ_STRIDE + k] = (char)q1;
        q2s[tc * WQ_STRIDE + k] = (char)q2;
    }
    __syncthreads();

    int8_t* slotbase = wq + (size_t)slot * WSLOT;
    int nblk = n0 >> 7;
    for (int i = t; i < 32 * 64; i += 256) {
        int row = i >> 6;
        int c16 = i & 63;
        int nr  = (n0 & 127) + row;
        int ks  = c16 >> 1;
        uint32_t off = sw_off(nr, c16 & 1);
        size_t cell = (size_t)(nblk * 32 + ks) * CELL;
        *(uint4*)(slotbase + cell +        off) = *(const uint4*)(q1s + row * WQ_STRIDE + c16 * 16);
        *(uint4*)(slotbase + cell + 4096 + off) = *(const uint4*)(q2s + row * WQ_STRIDE + c16 * 16);
    }
}

// ---------------- rowwise 2-digit quantization helpers ----------------
__device__ __forceinline__ float block_rowmax(float m, float* red) {
    int t = threadIdx.x;
    #pragma unroll
    for (int o = 16; o > 0; o >>= 1)
        m = fmaxf(m, __shfl_xor_sync(0xffffffff, m, o));
    if ((t & 31) == 0) red[t >> 5] = m;
    __syncthreads();
    if (t < 32) {
        float v = (t < 8) ? red[t] : 0.f;
        #pragma unroll
        for (int o = 4; o > 0; o >>= 1)
            v = fmaxf(v, __shfl_xor_sync(0xffffffff, v, o));
        if (t == 0) red[0] = fmaxf(v, 1e-30f);
    }
    __syncthreads();
    return red[0];
}

__device__ __forceinline__ void quant4_store(float o0, float o1, float o2, float o3,
                                             float inv, int row, int t,
                                             int8_t* __restrict__ qa) {
    float x0 = o0 * inv, x1 = o1 * inv, x2 = o2 * inv, x3 = o3 * inv;
    int a0 = __float2int_rn(x0), a1 = __float2int_rn(x1);
    int a2 = __float2int_rn(x2), a3 = __float2int_rn(x3);
    int b0 = clampi(__float2int_rn((x0 - a0) * 256.f), -127, 127);
    int b1 = clampi(__float2int_rn((x1 - a1) * 256.f), -127, 127);
    int b2 = clampi(__float2int_rn((x2 - a2) * 256.f), -127, 127);
    int b3 = clampi(__float2int_rn((x3 - a3) * 256.f), -127, 127);
    char4 c1; c1.x = (char)a0; c1.y = (char)a1; c1.z = (char)a2; c1.w = (char)a3;
    char4 c2; c2.x = (char)b0; c2.y = (char)b1; c2.z = (char)b2; c2.w = (char)b3;
    int rb = row >> 7, r = row & 127;
    int k  = t * 4;
    int ks = k >> 5, kc = k & 31;
    uint32_t off = sw_off(r, kc >> 4) + (kc & 15);
    size_t cell = (size_t)(rb * 32 + ks) * CELL;
    *(char4*)(qa + cell +        off) = c1;
    *(char4*)(qa + cell + 4096 + off) = c2;
}

// ---------------- layernorm + quantize ----------------
__global__ __launch_bounds__(256) void ln_quant_kernel(
        const float* __restrict__ x,
        const float* __restrict__ gamma, const float* __restrict__ beta,
        int8_t* __restrict__ qa, float* __restrict__ sa) {
    __shared__ float red_s[8];
    __shared__ float red_q[8];
    __shared__ float red_m[8];
    int row = blockIdx.x;
    int t = threadIdx.x;
    float4 v = ((const float4*)(x + (size_t)row * Dd))[t];
    float s  = v.x + v.y + v.z + v.w;
    float ss = v.x*v.x + v.y*v.y + v.z*v.z + v.w*v.w;
    #pragma unroll
    for (int o = 16; o > 0; o >>= 1) {
        s  += __shfl_xor_sync(0xffffffff, s,  o);
        ss += __shfl_xor_sync(0xffffffff, ss, o);
    }
    if ((t & 31) == 0) { red_s[t >> 5] = s; red_q[t >> 5] = ss; }
    __syncthreads();
    if (t < 32) {
        float a = (t < 8) ? red_s[t] : 0.f;
        float b = (t < 8) ? red_q[t] : 0.f;
        #pragma unroll
        for (int o = 4; o > 0; o >>= 1) {
            a += __shfl_xor_sync(0xffffffff, a, o);
            b += __shfl_xor_sync(0xffffffff, b, o);
        }
        if (t == 0) { red_s[0] = a; red_q[0] = b; }
    }
    __syncthreads();
    float mu  = red_s[0] * (1.0f / Dd);
    float var = red_q[0] * (1.0f / Dd) - mu * mu;
    float inv = rsqrtf(var + 1e-5f);
    float4 g4 = ((const float4*)gamma)[t];
    float4 b4 = ((const float4*)beta)[t];
    float o0 = (v.x - mu) * inv * g4.x + b4.x;
    float o1 = (v.y - mu) * inv * g4.y + b4.y;
    float o2 = (v.z - mu) * inv * g4.z + b4.z;
    float o3 = (v.w - mu) * inv * g4.w + b4.w;
    float m = fmaxf(fmaxf(fabsf(o0), fabsf(o1)), fmaxf(fabsf(o2), fabsf(o3)));
    float rmax = block_rowmax(m, red_m);
    if (t == 0) sa[row] = rmax * (1.0f / 127.0f);
    quant4_store(o0, o1, o2, o3, 127.0f / rmax, row, t, qa);
}

// ---------------- plain rowwise quantization ----------------
__global__ __launch_bounds__(256) void quant_kernel(
        const float* __restrict__ x,
        int8_t* __restrict__ qa, float* __restrict__ sa) {
    __shared__ float red_m[8];
    int row = blockIdx.x;
    int t = threadIdx.x;
    float4 v = ((const float4*)(x + (size_t)row * Dd))[t];
    float m = fmaxf(fmaxf(fabsf(v.x), fabsf(v.y)), fmaxf(fabsf(v.z), fabsf(v.w)));
    float rmax = block_rowmax(m, red_m);
    if (t == 0) sa[row] = rmax * (1.0f / 127.0f);
    quant4_store(v.x, v.y, v.z, v.w, 127.0f / rmax, row, t, qa);
}

// ---------------- linear-RNN scan over uv[row][2048]: writes gate fp32 ----
__global__ __launch_bounds__(256) void scan_kernel(const float* __restrict__ uv,
                                                   const float* __restrict__ theta,
                                                   float* __restrict__ w) {
    int tid = blockIdx.x * 256 + threadIdx.x;
    int b   = tid / NB;
    int blk = tid % NB;
    float th = theta[blk];
    float c = cosf(th), sn = sinf(th);
    float hx = 0.f, hy = 0.f;
    const float2* up = (const float2*)uv + (size_t)b * Ss * Dd + blk;   // stride Dd float2
    const float2* vp = up + (Dd / 2);
    float2*       wp = (float2*)w + (size_t)b * Ss * (Dd / 2) + blk;
    for (int s0 = 0; s0 < Ss; s0 += 8) {
        float2 ub[8], vb[8];
        #pragma unroll
        for (int j = 0; j < 8; j++) {
            ub[j] = up[(size_t)(s0 + j) * Dd];
            vb[j] = vp[(size_t)(s0 + j) * Dd];
        }
        #pragma unroll
        for (int j = 0; j < 8; j++) {
            float nx = c * hx - sn * hy + ub[j].x;
            float ny = sn * hx + c  * hy + ub[j].y;
            hx = nx; hy = ny;
            wp[(size_t)(s0 + j) * (Dd / 2)] = make_float2(hx * vb[j].x, hy * vb[j].y);
        }
    }
}

// ---------------- int8 two-digit GEMM (warp-specialized producer) ---------
// C = sA sB (q1a q1b^T + (q1a q2b^T + q2a q1b^T)/256) + bias (+Cin) (relu)
// 288 threads: warps 0-7 compute (4M x 2N, warp tile 32x32), warp 8 = producer.
// 128x64 CTA tile, k-slab 32, 2 CTAs/SM. Resubmission of R11 (infra flake).
#define NSTG   6
#define STAGEB 12288     // A 8KB + B 4KB

__device__ __forceinline__ uint32_t smem_u32(const void* p) {
    uint32_t a;
    asm("{ .reg .u64 t; cvta.to.shared.u64 t, %1; cvt.u32.u64 %0, t; }"
        : "=r"(a) : "l"(p));
    return a;
}
#define MBARRIER_INIT(addr, cnt) \
    asm volatile("mbarrier.init.shared.b64 [%0], %1;" :: "r"((uint32_t)(addr)), "r"((uint32_t)(cnt)) : "memory")
#define MBARRIER_EXPECT_TX(addr, bytes) \
    asm volatile("mbarrier.arrive.expect_tx.shared.b64 _, [%0], %1;" \
                 :: "r"((uint32_t)(addr)), "r"((uint32_t)(bytes)) : "memory")
#define MBARRIER_ARRIVE(addr) \
    asm volatile("mbarrier.arrive.shared.b64 _, [%0];" :: "r"((uint32_t)(addr)) : "memory")
#define MBARRIER_WAIT_PARITY(addr, par) do { \
    uint32_t _m = (uint32_t)(addr), _p = (uint32_t)(par), _d; \
    asm volatile("{\n\t.reg .pred p;\n\t" \
        "mbarrier.try_wait.parity.acquire.cta.shared::cta.b64 p, [%1], %2;\n\t" \
        "selp.b32 %0, 1, 0, p;\n\t}" : "=r"(_d) : "r"(_m), "r"(_p) : "memory"); \
    if (!_d) { \
        asm volatile("{\n\t.reg .pred P1;\n\tWL_%=:\n\t" \
            "mbarrier.try_wait.parity.acquire.cta.shared::cta.b64 P1, [%0], %1, 0x989680;\n\t" \
            "@P1 bra.uni WD_%=;\n\tbra.uni WL_%=;\n\tWD_%=:\n\t}" \
            :: "r"(_m), "r"(_p) : "memory"); \
    } \
} while(0)
#define BULK_G2S(smem, gmem, bytes, mbar) \
    asm volatile("cp.async.bulk.shared::cluster.global.mbarrier::complete_tx::bytes " \
                 "[%0], [%1], %2, [%3];" \
                 :: "r"((uint32_t)(smem)), "l"(gmem), "r"((uint32_t)(bytes)), \
                    "r"((uint32_t)(mbar)) : "memory")
#define FENCE_ASYNC() \
    asm volatile("fence.proxy.async.shared::cta;" ::: "memory")
#define LDSM4(r, addr) \
    asm volatile("ldmatrix.sync.aligned.m8n8.x4.shared.b16 {%0,%1,%2,%3}, [%4];" \
                 : "=r"((r)[0]), "=r"((r)[1]), "=r"((r)[2]), "=r"((r)[3]) \
                 : "r"(addr))
#define MMA_S8(ac, a, b0, b1) \
    asm volatile("mma.sync.aligned.m16n8k32.row.col.s32.s8.s8.s32 " \
                 "{%0,%1,%2,%3},{%4,%5,%6,%7},{%8,%9},{%0,%1,%2,%3};\n" \
                 : "+r"((ac)[0]), "+r"((ac)[1]), "+r"((ac)[2]), "+r"((ac)[3]) \
                 : "r"((a)[0]), "r"((a)[1]), "r"((a)[2]), "r"((a)[3]), \
                   "r"(b0), "r"(b1))

__global__ __launch_bounds__(288, 2) void gemm_s8_kernel(
        const int8_t* __restrict__ Aq, const float* __restrict__ sA,
        const int8_t* __restrict__ Bq, const float* __restrict__ sB,
        const float* __restrict__ bias, const float* __restrict__ Cin,
        float* __restrict__ C, int Ndim, int flags) {
    extern __shared__ __align__(128) char smem[];
    const uint32_t sb    = smem_u32(smem);       // full[s] at sb + s*8
    const uint32_t EMPTY = sb + NSTG * 8;        // empty[s]
    const uint32_t DATA  = sb + 128;

    int bx = blockIdx.x;            // 64-wide N tile
    int by = blockIdx.y;            // 128-high M tile
    int tid = threadIdx.x;
    int lane = tid & 31;

    const int8_t* srcA = Aq + (size_t)by * BLKSZ;
    const int8_t* srcB = Bq + (size_t)(bx >> 1) * BLKSZ;
    uint32_t halfoff = (uint32_t)(bx & 1) * 2048;

    if (tid == 0) {
        #pragma unroll
        for (int s = 0; s < NSTG; s++) {
            MBARRIER_INIT(sb + s * 8, 1);
            MBARRIER_INIT(EMPTY + s * 8, 256);   // compute threads only
        }
    }
    __syncthreads();

    const int NIT = Dd / 32;   // 32 slabs

    if (tid >= 256) {
        // -------- producer warp (warp 8) --------
        if (lane == 0) {
            FENCE_ASYNC();
            for (int it = 0; it < NIT; it++) {
                int s = it % NSTG;
                int wph = it / NSTG;
                if (wph >= 1) MBARRIER_WAIT_PARITY(EMPTY + s * 8, (wph - 1) & 1);
                MBARRIER_EXPECT_TX(sb + s * 8, STAGEB);
                BULK_G2S(DATA + s * STAGEB,         srcA + (size_t)it * CELL, CELL, sb + s * 8);
                BULK_G2S(DATA + s * STAGEB +  8192, srcB + (size_t)it * CELL + halfoff, 2048, sb + s * 8);
                BULK_G2S(DATA + s * STAGEB + 10240, srcB + (size_t)it * CELL + 4096 + halfoff, 2048, sb + s * 8);
            }
        }
        return;   // producer warp done (bulk ops complete asynchronously)
    }

    // -------- compute warps 0-7 --------
    int warp = tid >> 5;
    int g = lane >> 2;
    int q = lane & 3;
    int warpM = (warp & 3) * 32;    // 4 warps along M=128
    int warpN = (warp >> 2) * 32;   // 2 warps along N=64

    int r8  = lane & 7;
    int sub = lane >> 3;
    uint32_t aoff[2], boff[2];
    #pragma unroll
    for (int i = 0; i < 2; i++) {
        int mrow = warpM + i * 16 + (sub & 1) * 8 + r8;
        aoff[i] = sw_off(mrow, sub >> 1);
    }
    #pragma unroll
    for (int h = 0; h < 2; h++) {
        int nrow = warpN + h * 16 + (sub >> 1) * 8 + r8;   // 0..63 local
        boff[h] = 8192 + sw_off(nrow, sub & 1);
    }

    int accM[2][4][4], accC[2][4][4];
    #pragma unroll
    for (int i = 0; i < 2; i++)
        #pragma unroll
        for (int j = 0; j < 4; j++)
            #pragma unroll
            for (int r = 0; r < 4; r++) { accM[i][j][r] = 0; accC[i][j][r] = 0; }

    for (int it = 0; it < NIT; it++) {
        int st = it % NSTG;
        MBARRIER_WAIT_PARITY(sb + st * 8, (it / NSTG) & 1);

        uint32_t stg = DATA + st * STAGEB;
        uint32_t a1[2][4], a2[2][4], b1[2][4], b2[2][4];
        #pragma unroll
        for (int i = 0; i < 2; i++) {
            LDSM4(a1[i], stg        + aoff[i]);
            LDSM4(a2[i], stg + 4096 + aoff[i]);
        }
        #pragma unroll
        for (int h = 0; h < 2; h++) {
            LDSM4(b1[h], stg        + boff[h]);
            LDSM4(b2[h], stg + 2048 + boff[h]);
        }
        #pragma unroll
        for (int i = 0; i < 2; i++)
            #pragma unroll
            for (int j = 0; j < 4; j++) {
                int h = j >> 1, jj = (j & 1) * 2;
                MMA_S8(accM[i][j], a1[i], b1[h][jj], b1[h][jj + 1]);
                MMA_S8(accC[i][j], a1[i], b2[h][jj], b2[h][jj + 1]);
                MMA_S8(accC[i][j], a2[i], b1[h][jj], b1[h][jj + 1]);
            }
        MBARRIER_ARRIVE(EMPTY + st * 8);
    }

    // epilogue
    #pragma unroll
    for (int i = 0; i < 2; i++) {
        int r0 = by * 128 + warpM + i * 16 + g;
        int r1 = r0 + 8;
        float sa0 = sA[r0], sa1 = sA[r1];
        #pragma unroll
        for (int j = 0; j < 4; j++) {
            int cc = bx * 64 + warpN + j * 8 + (q << 1);
            float sb0 = sB[cc], sb1 = sB[cc + 1];
            float b0 = bias[cc], b1f = bias[cc + 1];
            float x0 = ((float)accM[i][j][0] + (float)accC[i][j][0] * (1.f/256.f)) * sa0 * sb0 + b0;
            float x1 = ((float)accM[i][j][1] + (float)accC[i][j][1] * (1.f/256.f)) * sa0 * sb1 + b1f;
            float x2 = ((float)accM[i][j][2] + (float)accC[i][j][2] * (1.f/256.f)) * sa1 * sb0 + b0;
            float x3 = ((float)accM[i][j][3] + (float)accC[i][j][3] * (1.f/256.f)) * sa1 * sb1 + b1f;
            if (flags & 1) {
                const float2 ci0 = *(const float2*)(Cin + (size_t)r0 * Ndim + cc);
                const float2 ci1 = *(const float2*)(Cin + (size_t)r1 * Ndim + cc);
                x0 += ci0.x; x1 += ci0.y; x2 += ci1.x; x3 += ci1.y;
            }
            if (flags & 2) {
                x0 = fmaxf(x0, 0.f); x1 = fmaxf(x1, 0.f);
                x2 = fmaxf(x2, 0.f); x3 = fmaxf(x3, 0.f);
            }
            *(float2*)(C + (size_t)r0 * Ndim + cc) = make_float2(x0, x1);
            *(float2*)(C + (size_t)r1 * Ndim + cc) = make_float2(x2, x3);
        }
    }
}

// ---------------- driver ----------------
extern "C" void kernel_launch(void* const* d_in, const int* in_sizes, int n_in,
                              void* d_out, int out_size) {
    const int*   input_x = (const int*)  d_in[0];
    const float* emb     = (const float*)d_in[1];
    const float* theta   = (const float*)d_in[2];
    const float* Wx      = (const float*)d_in[3];
    const float* bx_     = (const float*)d_in[4];
    const float* Wv      = (const float*)d_in[5];
    const float* bv      = (const float*)d_in[6];
    const float* Wh      = (const float*)d_in[7];
    const float* bh      = (const float*)d_in[8];
    const float* ln_g    = (const float*)d_in[9];
    const float* ln_b    = (const float*)d_in[10];
    const float* lnf_g   = (const float*)d_in[11];
    const float* lnf_b   = (const float*)d_in[12];
    const float* Wo1     = (const float*)d_in[13];
    const float* bo1     = (const float*)d_in[14];
    const float* Wo2     = (const float*)d_in[15];
    const float* bo2     = (const float*)d_in[16];

    float *a, *uv, *w, *sa, *sw, *bc;
    int8_t *qa, *wq;
    cudaGetSymbolAddress((void**)&a,  g_a);
    cudaGetSymbolAddress((void**)&uv, g_uv);
    cudaGetSymbolAddress((void**)&w,  g_w);
    cudaGetSymbolAddress((void**)&qa, g_qa);
    cudaGetSymbolAddress((void**)&sa, g_sa);
    cudaGetSymbolAddress((void**)&wq, g_wq);
    cudaGetSymbolAddress((void**)&sw, g_sw);
    cudaGetSymbolAddress((void**)&bc, g_bc);

    const int WQSMEM = 64 * WQ_STRIDE + (8 * 32 + 32) * 4;
    const int GSMEM  = 128 + NSTG * STAGEB;   // 73856
    cudaFuncSetAttribute(wquant_kernel,
                         cudaFuncAttributeMaxDynamicSharedMemorySize, WQSMEM);
    cudaFuncSetAttribute(gemm_s8_kernel,
                         cudaFuncAttributeMaxDynamicSharedMemorySize, GSMEM);

    // launch 0: weights + bias concat ; 1: embed ; 2: ln_quant ;
    // launch 3: first gemm (ncu capture target)
    wquant_kernel<<<dim3(32, 14), 256, WQSMEM>>>(Wx, Wv, Wh, Wo1, Wo2,
                                                 bx_, bv, wq, sw, bc);
    embed_kernel<<<ROWS, 256>>>(input_x, emb, a);

    dim3 grid_XV(2 * Dd / 64, ROWS / 128);   // (32, 256) combined Wx|Wv
    dim3 grid_DD(Dd / 64, ROWS / 128);       // (16, 256)
    dim3 grid_DV(Vv / 64, ROWS / 128);       // (2, 256)

    for (int l = 0; l < Ll; l++) {
        ln_quant_kernel<<<ROWS, 256>>>(a, ln_g + (size_t)l * Dd, ln_b + (size_t)l * Dd,
                                       qa, sa);
        gemm_s8_kernel<<<grid_XV, 288, GSMEM>>>(qa, sa,
                wq + (size_t)(2 * l) * WSLOT, sw + (size_t)(2 * l) * Dd,
                bc + (size_t)l * 2 * Dd, nullptr, uv, 2 * Dd, 0);
        scan_kernel<<<(Bb * NB) / 256, 256>>>(uv, theta + (size_t)l * NB, w);
        quant_kernel<<<ROWS, 256>>>(w, qa, sa);
        int flags = (l < Ll - 1) ? 1 : 0;
        gemm_s8_kernel<<<grid_DD, 288, GSMEM>>>(qa, sa,
                wq + (size_t)(8 + l) * WSLOT, sw + (size_t)(8 + l) * Dd,
                bh + (size_t)l * Dd, a, a, Dd, flags);
    }

    ln_quant_kernel<<<ROWS, 256>>>(a, lnf_g, lnf_b, qa, sa);
    gemm_s8_kernel<<<grid_DD, 288, GSMEM>>>(qa, sa,
            wq + (size_t)12 * WSLOT, sw + (size_t)12 * Dd, bo1, nullptr, w, Dd, 2);
    quant_kernel<<<ROWS, 256>>>(w, qa, sa);
    gemm_s8_kernel<<<grid_DV, 288, GSMEM>>>(qa, sa,
            wq + (size_t)13 * WSLOT, sw + (size_t)13 * Dd, bo2, nullptr,
            (float*)d_out, Vv, 0);
}

// round 17
// speedup vs baseline: 1.3290x; 1.3290x over previous
#include <cuda_runtime.h>
#include <cuda_bf16.h>
#include <cstdint>

// Problem constants
#define Bb 16
#define Ss 2048
#define Dd 1024
#define Vv 128          // vocab
#define Ll 4
#define NB (Dd/2)       // rotation blocks = 512
#define ROWS (Bb*Ss)    // 32768
#define DD2 (Dd*Dd)     // 1048576
#define SSEG 16         // scan segments per chain
#define LSEG (Ss/SSEG)  // 128 steps per segment
#define NCHAIN (Bb*NB)  // 8192 scan chains

// Tiled operand layout: [blk128][kslab32][digit2][row128][k32] bytes.
#define CELL   8192
#define BLKSZ  (32 * CELL)          // 256 KB per 128-row block (full K)
#define WSLOT  (8 * BLKSZ)          // 2 MB per DxD weight slot

// ---------------- scratch (device globals; no allocation allowed) ----------
__device__ float g_a [ROWS*Dd];          // residual stream
__device__ float g_uv[(size_t)ROWS*2*Dd];// combined u|v  [row][2048]
__device__ float g_w [ROWS*Dd];          // gate / relu out (fp32, pre-quant)
__device__ float g_E [NCHAIN*SSEG*2];    // scan segment end-states / carries
__device__ __align__(128) int8_t g_qa[(size_t)ROWS*Dd*2];           // tiled activations
__device__ float  g_sa [ROWS];           // activation row scales
// slots: 2l=Wx_l, 2l+1=Wv_l (l=0..3), 8+l=Wh_l, 12=Wo1, 13=Wo2
__device__ __align__(128) int8_t g_wq[(size_t)13*WSLOT + 2*BLKSZ];
__device__ float  g_sw [14*Dd];          // weight col scales (slot-major)
__device__ float  g_bc [Ll*2*Dd];        // concat biases [l][bx|bv]

__device__ __forceinline__ int clampi(int x, int lo, int hi) {
    return x < lo ? lo : (x > hi ? hi : x);
}
__device__ __forceinline__ uint32_t sw_off(int r, int c16) {
    return (uint32_t)(r * 32 + ((c16 ^ ((r >> 2) & 1)) << 4));
}

// ---------------- embedding gather ----------------
__global__ __launch_bounds__(256) void embed_kernel(const int* __restrict__ idx,
                                                    const float* __restrict__ emb,
                                                    float* __restrict__ a) {
    int i = blockIdx.x * 256 + threadIdx.x;
    int row = i >> 8;
    int col = i & 255;
    int tok = idx[row];
    ((float4*)a)[i] = ((const float4*)emb)[tok * 256 + col];
}

// ---------------- weight transpose + 2-digit int8 quant (tiled out) -------
#define WQ_STRIDE 1040
__global__ __launch_bounds__(256) void wquant_kernel(
        const float* __restrict__ Wx, const float* __restrict__ Wv,
        const float* __restrict__ Wh, const float* __restrict__ Wo1,
        const float* __restrict__ Wo2,
        const float* __restrict__ bxv, const float* __restrict__ bvv,
        int8_t* __restrict__ wq, float* __restrict__ sw,
        float* __restrict__ bc, int slot0) {
    extern __shared__ char wsm[];
    char*  q1s  = wsm;
    char*  q2s  = wsm + 32 * WQ_STRIDE;
    float* part = (float*)(wsm + 64 * WQ_STRIDE);
    float* cmax = part + 8 * 32;

    int slot = slot0 + blockIdx.y;
    const float* W;
    int Ndim = Dd;
    if (slot < 8)        W = ((slot & 1) ? Wv : Wx) + (size_t)(slot >> 1) * DD2;
    else if (slot < 12)  W = Wh + (size_t)(slot - 8) * DD2;
    else if (slot == 12) W = Wo1;
    else { W = Wo2; Ndim = Vv; }

    int t = threadIdx.x;
    if (slot < 8 && blockIdx.x == 0) {
        int l = slot >> 1;
        const float* src = ((slot & 1) ? bvv : bxv) + (size_t)l * Dd;
        float* dst = bc + (size_t)l * 2 * Dd + (slot & 1) * Dd;
        for (int i = t; i < Dd; i += 256) dst[i] = src[i];
    }

    int n0 = blockIdx.x * 32;
    if (n0 >= Ndim) return;
    int tc = t & 31, tr = t >> 5;

    float m = 0.f;
    #pragma unroll 4
    for (int k = tr; k < Dd; k += 8)
        m = fmaxf(m, fabsf(W[(size_t)k * Ndim + n0 + tc]));
    part[tr * 32 + tc] = m;
    __syncthreads();
    if (t < 32) {
        float mm = part[t];
        #pragma unroll
        for (int r = 1; r < 8; r++) mm = fmaxf(mm, part[r * 32 + t]);
        mm = fmaxf(mm, 1e-30f);
        cmax[t] = mm;
        sw[slot * Dd + n0 + t] = mm * (1.0f / 127.0f);
    }
    __syncthreads();

    float inv = 127.0f / cmax[tc];
    #pragma unroll 4
    for (int k = tr; k < Dd; k += 8) {
        float x = W[(size_t)k * Ndim + n0 + tc] * inv;
        int q1 = __float2int_rn(x);
        float r = x - (float)q1;
        int q2 = clampi(__float2int_rn(r * 256.0f), -127, 127);
        q1s[tc * WQ_STRIDE + k] = (char)q1;
        q2s[tc * WQ_STRIDE + k] = (char)q2;
    }
    __syncthreads();

    int8_t* slotbase = wq + (size_t)slot * WSLOT;
    int nblk = n0 >> 7;
    for (int i = t; i < 32 * 64; i += 256) {
        int row = i >> 6;
        int c16 = i & 63;
        int nr  = (n0 & 127) + row;
        int ks  = c16 >> 1;
        uint32_t off = sw_off(nr, c16 & 1);
        size_t cell = (size_t)(nblk * 32 + ks) * CELL;
        *(uint4*)(slotbase + cell +        off) = *(const uint4*)(q1s + row * WQ_STRIDE + c16 * 16);
        *(uint4*)(slotbase + cell + 4096 + off) = *(const uint4*)(q2s + row * WQ_STRIDE + c16 * 16);
    }
}

// ---------------- rowwise 2-digit quantization helpers ----------------
__device__ __forceinline__ float block_rowmax(float m, float* red) {
    int t = threadIdx.x;
    #pragma unroll
    for (int o = 16; o > 0; o >>= 1)
        m = fmaxf(m, __shfl_xor_sync(0xffffffff, m, o));
    if ((t & 31) == 0) red[t >> 5] = m;
    __syncthreads();
    if (t < 32) {
        float v = (t < 8) ? red[t] : 0.f;
        #pragma unroll
        for (int o = 4; o > 0; o >>= 1)
            v = fmaxf(v, __shfl_xor_sync(0xffffffff, v, o));
        if (t == 0) red[0] = fmaxf(v, 1e-30f);
    }
    __syncthreads();
    return red[0];
}

__device__ __forceinline__ void quant4_store(float o0, float o1, float o2, float o3,
                                             float inv, int row, int t,
                                             int8_t* __restrict__ qa) {
    float x0 = o0 * inv, x1 = o1 * inv, x2 = o2 * inv, x3 = o3 * inv;
    int a0 = __float2int_rn(x0), a1 = __float2int_rn(x1);
    int a2 = __float2int_rn(x2), a3 = __float2int_rn(x3);
    int b0 = clampi(__float2int_rn((x0 - a0) * 256.f), -127, 127);
    int b1 = clampi(__float2int_rn((x1 - a1) * 256.f), -127, 127);
    int b2 = clampi(__float2int_rn((x2 - a2) * 256.f), -127, 127);
    int b3 = clampi(__float2int_rn((x3 - a3) * 256.f), -127, 127);
    char4 c1; c1.x = (char)a0; c1.y = (char)a1; c1.z = (char)a2; c1.w = (char)a3;
    char4 c2; c2.x = (char)b0; c2.y = (char)b1; c2.z = (char)b2; c2.w = (char)b3;
    int rb = row >> 7, r = row & 127;
    int k  = t * 4;
    int ks = k >> 5, kc = k & 31;
    uint32_t off = sw_off(r, kc >> 4) + (kc & 15);
    size_t cell = (size_t)(rb * 32 + ks) * CELL;
    *(char4*)(qa + cell +        off) = c1;
    *(char4*)(qa + cell + 4096 + off) = c2;
}

// ---------------- layernorm + quantize ----------------
__global__ __launch_bounds__(256) void ln_quant_kernel(
        const float* __restrict__ x,
        const float* __restrict__ gamma, const float* __restrict__ beta,
        int8_t* __restrict__ qa, float* __restrict__ sa) {
    __shared__ float red_s[8];
    __shared__ float red_q[8];
    __shared__ float red_m[8];
    int row = blockIdx.x;
    int t = threadIdx.x;
    float4 v = ((const float4*)(x + (size_t)row * Dd))[t];
    float s  = v.x + v.y + v.z + v.w;
    float ss = v.x*v.x + v.y*v.y + v.z*v.z + v.w*v.w;
    #pragma unroll
    for (int o = 16; o > 0; o >>= 1) {
        s  += __shfl_xor_sync(0xffffffff, s,  o);
        ss += __shfl_xor_sync(0xffffffff, ss, o);
    }
    if ((t & 31) == 0) { red_s[t >> 5] = s; red_q[t >> 5] = ss; }
    __syncthreads();
    if (t < 32) {
        float a = (t < 8) ? red_s[t] : 0.f;
        float b = (t < 8) ? red_q[t] : 0.f;
        #pragma unroll
        for (int o = 4; o > 0; o >>= 1) {
            a += __shfl_xor_sync(0xffffffff, a, o);
            b += __shfl_xor_sync(0xffffffff, b, o);
        }
        if (t == 0) { red_s[0] = a; red_q[0] = b; }
    }
    __syncthreads();
    float mu  = red_s[0] * (1.0f / Dd);
    float var = red_q[0] * (1.0f / Dd) - mu * mu;
    float inv = rsqrtf(var + 1e-5f);
    float4 g4 = ((const float4*)gamma)[t];
    float4 b4 = ((const float4*)beta)[t];
    float o0 = (v.x - mu) * inv * g4.x + b4.x;
    float o1 = (v.y - mu) * inv * g4.y + b4.y;
    float o2 = (v.z - mu) * inv * g4.z + b4.z;
    float o3 = (v.w - mu) * inv * g4.w + b4.w;
    float m = fmaxf(fmaxf(fabsf(o0), fabsf(o1)), fmaxf(fabsf(o2), fabsf(o3)));
    float rmax = block_rowmax(m, red_m);
    if (t == 0) sa[row] = rmax * (1.0f / 127.0f);
    quant4_store(o0, o1, o2, o3, 127.0f / rmax, row, t, qa);
}

// ---------------- plain rowwise quantization ----------------
__global__ __launch_bounds__(256) void quant_kernel(
        const float* __restrict__ x,
        int8_t* __restrict__ qa, float* __restrict__ sa) {
    __shared__ float red_m[8];
    int row = blockIdx.x;
    int t = threadIdx.x;
    float4 v = ((const float4*)(x + (size_t)row * Dd))[t];
    float m = fmaxf(fmaxf(fabsf(v.x), fabsf(v.y)), fmaxf(fabsf(v.z), fabsf(v.w)));
    float rmax = block_rowmax(m, red_m);
    if (t == 0) sa[row] = rmax * (1.0f / 127.0f);
    quant4_store(v.x, v.y, v.z, v.w, 127.0f / rmax, row, t, qa);
}

// ---------------- segmented linear-RNN scan ----------------
// h_t = R(theta) h_{t-1} + u_t over 2048 steps, split into SSEG=16 segments.
// scanA: local scan per segment from zero; E[seg][chain] = segment end state.
// scanB: per chain sequential carry: carry_s = R^LSEG carry_{s-1} + E_{s-1};
//        overwrites E[seg][chain] with the state ENTERING segment seg.
// scanC: rescan each segment from its carry; writes gate w = h * v.
__global__ __launch_bounds__(256) void scanA_kernel(const float* __restrict__ uv,
                                                    const float* __restrict__ theta,
                                                    float* __restrict__ E) {
    int gidx = blockIdx.x * 256 + threadIdx.x;   // 0 .. NCHAIN*SSEG-1
    int chain = gidx & (NCHAIN - 1);
    int seg   = gidx >> 13;                      // NCHAIN = 8192 = 2^13
    int b = chain / NB, blk = chain % NB;
    float th = theta[blk];
    float c = cosf(th), sn = sinf(th);
    float hx = 0.f, hy = 0.f;
    const float2* up = (const float2*)uv + (size_t)b * Ss * Dd + blk;  // stride Dd f2/row
    int t0 = seg * LSEG;
    for (int s0 = 0; s0 < LSEG; s0 += 8) {
        float2 ub[8];
        #pragma unroll
        for (int j = 0; j < 8; j++)
            ub[j] = up[(size_t)(t0 + s0 + j) * Dd];
        #pragma unroll
        for (int j = 0; j < 8; j++) {
            float nx = c * hx - sn * hy + ub[j].x;
            float ny = sn * hx + c  * hy + ub[j].y;
            hx = nx; hy = ny;
        }
    }
    ((float2*)E)[seg * NCHAIN + chain] = make_float2(hx, hy);
}

__global__ __launch_bounds__(256) void scanB_kernel(const float* __restrict__ theta,
                                                    float* __restrict__ E) {
    int chain = blockIdx.x * 256 + threadIdx.x;  // 0..NCHAIN-1
    int blk = chain % NB;
    float th = theta[blk];
    float c = cosf(th), sn = sinf(th);
    // R^LSEG via 7 doublings (LSEG = 128 = 2^7)
    float cc = c, ss = sn;
    #pragma unroll
    for (int i = 0; i < 7; i++) {
        float c2 = cc * cc - ss * ss;
        float s2 = 2.f * cc * ss;
        cc = c2; ss = s2;
    }
    float2* Ep = (float2*)E;
    float cx = 0.f, cy = 0.f;
    #pragma unroll
    for (int s = 0; s < SSEG; s++) {
        float2 e = Ep[s * NCHAIN + chain];
        Ep[s * NCHAIN + chain] = make_float2(cx, cy);
        float nx = cc * cx - ss * cy + e.x;
        float ny = ss * cx + cc * cy + e.y;
        cx = nx; cy = ny;
    }
}

__global__ __launch_bounds__(256) void scanC_kernel(const float* __restrict__ uv,
                                                    const float* __restrict__ theta,
                                                    const float* __restrict__ E,
                                                    float* __restrict__ w) {
    int gidx = blockIdx.x * 256 + threadIdx.x;
    int chain = gidx & (NCHAIN - 1);
    int seg   = gidx >> 13;
    int b = chain / NB, blk = chain % NB;
    float th = theta[blk];
    float c = cosf(th), sn = sinf(th);
    float2 h0 = ((const float2*)E)[seg * NCHAIN + chain];
    float hx = h0.x, hy = h0.y;
    const float2* up = (const float2*)uv + (size_t)b * Ss * Dd + blk;
    const float2* vp = up + (Dd / 2);
    float2*       wp = (float2*)w + (size_t)b * Ss * (Dd / 2) + blk;
    int t0 = seg * LSEG;
    for (int s0 = 0; s0 < LSEG; s0 += 8) {
        float2 ub[8], vb[8];
        #pragma unroll
        for (int j = 0; j < 8; j++) {
            ub[j] = up[(size_t)(t0 + s0 + j) * Dd];
            vb[j] = vp[(size_t)(t0 + s0 + j) * Dd];
        }
        #pragma unroll
        for (int j = 0; j < 8; j++) {
            float nx = c * hx - sn * hy + ub[j].x;
            float ny = sn * hx + c  * hy + ub[j].y;
            hx = nx; hy = ny;
            wp[(size_t)(t0 + s0 + j) * (Dd / 2)] = make_float2(hx * vb[j].x, hy * vb[j].y);
        }
    }
}

// ---------------- int8 two-digit GEMM (R10 config: inline producer) -------
// C = sA sB (q1a q1b^T + (q1a q2b^T + q2a q1b^T)/256) + bias (+Cin) (relu)
// 256 threads, 8 warps (4M x 2N), warp tile 32x32, 128x64 CTA, 2 CTAs/SM.
#define NSTG   5
#define STAGEB 12288     // A 8KB + B 4KB

__device__ __forceinline__ uint32_t smem_u32(const void* p) {
    uint32_t a;
    asm("{ .reg .u64 t; cvta.to.shared.u64 t, %1; cvt.u32.u64 %0, t; }"
        : "=r"(a) : "l"(p));
    return a;
}
#define MBARRIER_INIT(addr, cnt) \
    asm volatile("mbarrier.init.shared.b64 [%0], %1;" :: "r"((uint32_t)(addr)), "r"((uint32_t)(cnt)) : "memory")
#define MBARRIER_EXPECT_TX(addr, bytes) \
    asm volatile("mbarrier.arrive.expect_tx.shared.b64 _, [%0], %1;" \
                 :: "r"((uint32_t)(addr)), "r"((uint32_t)(bytes)) : "memory")
#define MBARRIER_ARRIVE(addr) \
    asm volatile("mbarrier.arrive.shared.b64 _, [%0];" :: "r"((uint32_t)(addr)) : "memory")
#define MBARRIER_WAIT_PARITY(addr, par) do { \
    uint32_t _m = (uint32_t)(addr), _p = (uint32_t)(par), _d; \
    asm volatile("{\n\t.reg .pred p;\n\t" \
        "mbarrier.try_wait.parity.acquire.cta.shared::cta.b64 p, [%1], %2;\n\t" \
        "selp.b32 %0, 1, 0, p;\n\t}" : "=r"(_d) : "r"(_m), "r"(_p) : "memory"); \
    if (!_d) { \
        asm volatile("{\n\t.reg .pred P1;\n\tWL_%=:\n\t" \
            "mbarrier.try_wait.parity.acquire.cta.shared::cta.b64 P1, [%0], %1, 0x989680;\n\t" \
            "@P1 bra.uni WD_%=;\n\tbra.uni WL_%=;\n\tWD_%=:\n\t}" \
            :: "r"(_m), "r"(_p) : "memory"); \
    } \
} while(0)
#define BULK_G2S(smem, gmem, bytes, mbar) \
    asm volatile("cp.async.bulk.shared::cluster.global.mbarrier::complete_tx::bytes " \
                 "[%0], [%1], %2, [%3];" \
                 :: "r"((uint32_t)(smem)), "l"(gmem), "r"((uint32_t)(bytes)), \
                    "r"((uint32_t)(mbar)) : "memory")
#define FENCE_ASYNC() \
    asm volatile("fence.proxy.async.shared::cta;" ::: "memory")
#define LDSM4(r, addr) \
    asm volatile("ldmatrix.sync.aligned.m8n8.x4.shared.b16 {%0,%1,%2,%3}, [%4];" \
                 : "=r"((r)[0]), "=r"((r)[1]), "=r"((r)[2]), "=r"((r)[3]) \
                 : "r"(addr))
#define MMA_S8(ac, a, b0, b1) \
    asm volatile("mma.sync.aligned.m16n8k32.row.col.s32.s8.s8.s32 " \
                 "{%0,%1,%2,%3},{%4,%5,%6,%7},{%8,%9},{%0,%1,%2,%3};\n" \
                 : "+r"((ac)[0]), "+r"((ac)[1]), "+r"((ac)[2]), "+r"((ac)[3]) \
                 : "r"((a)[0]), "r"((a)[1]), "r"((a)[2]), "r"((a)[3]), \
                   "r"(b0), "r"(b1))

__global__ __launch_bounds__(256, 2) void gemm_s8_kernel(
        const int8_t* __restrict__ Aq, const float* __restrict__ sA,
        const int8_t* __restrict__ Bq, const float* __restrict__ sB,
        const float* __restrict__ bias, const float* __restrict__ Cin,
        float* __restrict__ C, int Ndim, int flags) {
    extern __shared__ __align__(128) char smem[];
    const uint32_t sb    = smem_u32(smem);       // full[s] at sb + s*8
    const uint32_t EMPTY = sb + NSTG * 8;        // empty[s]
    const uint32_t DATA  = sb + 128;

    int bx = blockIdx.x;            // 64-wide N tile
    int by = blockIdx.y;            // 128-high M tile
    int tid = threadIdx.x;
    int warp = tid >> 5;
    int lane = tid & 31;
    int g = lane >> 2;
    int q = lane & 3;
    int warpM = (warp & 3) * 32;    // 4 warps along M=128
    int warpN = (warp >> 2) * 32;   // 2 warps along N=64

    const int8_t* srcA = Aq + (size_t)by * BLKSZ;
    const int8_t* srcB = Bq + (size_t)(bx >> 1) * BLKSZ;
    uint32_t halfoff = (uint32_t)(bx & 1) * 2048;

    if (tid == 0) {
        #pragma unroll
        for (int s = 0; s < NSTG; s++) {
            MBARRIER_INIT(sb + s * 8, 1);
            MBARRIER_INIT(EMPTY + s * 8, 256);
        }
    }
    __syncthreads();
    FENCE_ASYNC();

    if (tid == 0) {
        #pragma unroll
        for (int s = 0; s < NSTG - 1; s++) {
            MBARRIER_EXPECT_TX(sb + s * 8, STAGEB);
            BULK_G2S(DATA + s * STAGEB,         srcA + (size_t)s * CELL, CELL, sb + s * 8);
            BULK_G2S(DATA + s * STAGEB +  8192, srcB + (size_t)s * CELL + halfoff, 2048, sb + s * 8);
            BULK_G2S(DATA + s * STAGEB + 10240, srcB + (size_t)s * CELL + 4096 + halfoff, 2048, sb + s * 8);
        }
    }

    int r8  = lane & 7;
    int sub = lane >> 3;
    uint32_t aoff[2], boff[2];
    #pragma unroll
    for (int i = 0; i < 2; i++) {
        int mrow = warpM + i * 16 + (sub & 1) * 8 + r8;
        aoff[i] = sw_off(mrow, sub >> 1);
    }
    #pragma unroll
    for (int h = 0; h < 2; h++) {
        int nrow = warpN + h * 16 + (sub >> 1) * 8 + r8;   // 0..63 local
        boff[h] = 8192 + sw_off(nrow, sub & 1);
    }

    int accM[2][4][4], accC[2][4][4];
    #pragma unroll
    for (int i = 0; i < 2; i++)
        #pragma unroll
        for (int j = 0; j < 4; j++)
            #pragma unroll
            for (int r = 0; r < 4; r++) { accM[i][j][r] = 0; accC[i][j][r] = 0; }

    const int NIT = Dd / 32;

    for (int it = 0; it < NIT; it++) {
        int st = it % NSTG;
        MBARRIER_WAIT_PARITY(sb + st * 8, (it / NSTG) & 1);

        if (tid == 0 && it + NSTG - 1 < NIT) {
            if (it >= 1) {
                int s2 = (it - 1) % NSTG;
                MBARRIER_WAIT_PARITY(EMPTY + s2 * 8, ((it - 1) / NSTG) & 1);
                MBARRIER_EXPECT_TX(sb + s2 * 8, STAGEB);
                BULK_G2S(DATA + s2 * STAGEB,         srcA + (size_t)(it + NSTG - 1) * CELL, CELL, sb + s2 * 8);
                BULK_G2S(DATA + s2 * STAGEB +  8192, srcB + (size_t)(it + NSTG - 1) * CELL + halfoff, 2048, sb + s2 * 8);
                BULK_G2S(DATA + s2 * STAGEB + 10240, srcB + (size_t)(it + NSTG - 1) * CELL + 4096 + halfoff, 2048, sb + s2 * 8);
            } else {
                int s2 = NSTG - 1;
                MBARRIER_EXPECT_TX(sb + s2 * 8, STAGEB);
                BULK_G2S(DATA + s2 * STAGEB,         srcA + (size_t)(NSTG - 1) * CELL, CELL, sb + s2 * 8);
                BULK_G2S(DATA + s2 * STAGEB +  8192, srcB + (size_t)(NSTG - 1) * CELL + halfoff, 2048, sb + s2 * 8);
                BULK_G2S(DATA + s2 * STAGEB + 10240, srcB + (size_t)(NSTG - 1) * CELL + 4096 + halfoff, 2048, sb + s2 * 8);
            }
        }

        uint32_t stg = DATA + st * STAGEB;
        uint32_t a1[2][4], a2[2][4], b1[2][4], b2[2][4];
        #pragma unroll
        for (int i = 0; i < 2; i++) {
            LDSM4(a1[i], stg        + aoff[i]);
            LDSM4(a2[i], stg + 4096 + aoff[i]);
        }
        #pragma unroll
        for (int h = 0; h < 2; h++) {
            LDSM4(b1[h], stg        + boff[h]);
            LDSM4(b2[h], stg + 2048 + boff[h]);
        }
        #pragma unroll
        for (int i = 0; i < 2; i++)
            #pragma unroll
            for (int j = 0; j < 4; j++) {
                int h = j >> 1, jj = (j & 1) * 2;
                MMA_S8(accM[i][j], a1[i], b1[h][jj], b1[h][jj + 1]);
                MMA_S8(accC[i][j], a1[i], b2[h][jj], b2[h][jj + 1]);
                MMA_S8(accC[i][j], a2[i], b1[h][jj], b1[h][jj + 1]);
            }
        MBARRIER_ARRIVE(EMPTY + st * 8);
    }

    // epilogue
    #pragma unroll
    for (int i = 0; i < 2; i++) {
        int r0 = by * 128 + warpM + i * 16 + g;
        int r1 = r0 + 8;
        float sa0 = sA[r0], sa1 = sA[r1];
        #pragma unroll
        for (int j = 0; j < 4; j++) {
            int cc = bx * 64 + warpN + j * 8 + (q << 1);
            float sb0 = sB[cc], sb1 = sB[cc + 1];
            float b0 = bias[cc], b1f = bias[cc + 1];
            float x0 = ((float)accM[i][j][0] + (float)accC[i][j][0] * (1.f/256.f)) * sa0 * sb0 + b0;
            float x1 = ((float)accM[i][j][1] + (float)accC[i][j][1] * (1.f/256.f)) * sa0 * sb1 + b1f;
            float x2 = ((float)accM[i][j][2] + (float)accC[i][j][2] * (1.f/256.f)) * sa1 * sb0 + b0;
            float x3 = ((float)accM[i][j][3] + (float)accC[i][j][3] * (1.f/256.f)) * sa1 * sb1 + b1f;
            if (flags & 1) {
                const float2 ci0 = *(const float2*)(Cin + (size_t)r0 * Ndim + cc);
                const float2 ci1 = *(const float2*)(Cin + (size_t)r1 * Ndim + cc);
                x0 += ci0.x; x1 += ci0.y; x2 += ci1.x; x3 += ci1.y;
            }
            if (flags & 2) {
                x0 = fmaxf(x0, 0.f); x1 = fmaxf(x1, 0.f);
                x2 = fmaxf(x2, 0.f); x3 = fmaxf(x3, 0.f);
            }
            *(float2*)(C + (size_t)r0 * Ndim + cc) = make_float2(x0, x1);
            *(float2*)(C + (size_t)r1 * Ndim + cc) = make_float2(x2, x3);
        }
    }
}

// ---------------- driver ----------------
extern "C" void kernel_launch(void* const* d_in, const int* in_sizes, int n_in,
                              void* d_out, int out_size) {
    const int*   input_x = (const int*)  d_in[0];
    const float* emb     = (const float*)d_in[1];
    const float* theta   = (const float*)d_in[2];
    const float* Wx      = (const float*)d_in[3];
    const float* bx_     = (const float*)d_in[4];
    const float* Wv      = (const float*)d_in[5];
    const float* bv      = (const float*)d_in[6];
    const float* Wh      = (const float*)d_in[7];
    const float* bh      = (const float*)d_in[8];
    const float* ln_g    = (const float*)d_in[9];
    const float* ln_b    = (const float*)d_in[10];
    const float* lnf_g   = (const float*)d_in[11];
    const float* lnf_b   = (const float*)d_in[12];
    const float* Wo1     = (const float*)d_in[13];
    const float* bo1     = (const float*)d_in[14];
    const float* Wo2     = (const float*)d_in[15];
    const float* bo2     = (const float*)d_in[16];

    float *a, *uv, *w, *sa, *sw, *bc, *E;
    int8_t *qa, *wq;
    cudaGetSymbolAddress((void**)&a,  g_a);
    cudaGetSymbolAddress((void**)&uv, g_uv);
    cudaGetSymbolAddress((void**)&w,  g_w);
    cudaGetSymbolAddress((void**)&E,  g_E);
    cudaGetSymbolAddress((void**)&qa, g_qa);
    cudaGetSymbolAddress((void**)&sa, g_sa);
    cudaGetSymbolAddress((void**)&wq, g_wq);
    cudaGetSymbolAddress((void**)&sw, g_sw);
    cudaGetSymbolAddress((void**)&bc, g_bc);

    const int WQSMEM = 64 * WQ_STRIDE + (8 * 32 + 32) * 4;
    const int GSMEM  = 128 + NSTG * STAGEB;   // 61568
    cudaFuncSetAttribute(wquant_kernel,
                         cudaFuncAttributeMaxDynamicSharedMemorySize, WQSMEM);
    cudaFuncSetAttribute(gemm_s8_kernel,
                         cudaFuncAttributeMaxDynamicSharedMemorySize, GSMEM);

    // our launch 0: embed ; 1: ln_quant(l=0) ; 2: wquant part1 ;
    // 3: wquant part2  <- ncu capture target (-s 5 -c 1)
    embed_kernel<<<ROWS, 256>>>(input_x, emb, a);
    ln_quant_kernel<<<ROWS, 256>>>(a, ln_g, ln_b, qa, sa);
    wquant_kernel<<<dim3(32, 7), 256, WQSMEM>>>(Wx, Wv, Wh, Wo1, Wo2,
                                                bx_, bv, wq, sw, bc, 0);
    wquant_kernel<<<dim3(32, 7), 256, WQSMEM>>>(Wx, Wv, Wh, Wo1, Wo2,
                                                bx_, bv, wq, sw, bc, 7);

    dim3 grid_XV(2 * Dd / 64, ROWS / 128);   // (32, 256)
    dim3 grid_DD(Dd / 64, ROWS / 128);       // (16, 256)
    dim3 grid_DV(Vv / 64, ROWS / 128);       // (2, 256)
    const int SCAN_GRID = NCHAIN * SSEG / 256;   // 512

    for (int l = 0; l < Ll; l++) {
        if (l > 0)
            ln_quant_kernel<<<ROWS, 256>>>(a, ln_g + (size_t)l * Dd,
                                           ln_b + (size_t)l * Dd, qa, sa);
        gemm_s8_kernel<<<grid_XV, 256, GSMEM>>>(qa, sa,
                wq + (size_t)(2 * l) * WSLOT, sw + (size_t)(2 * l) * Dd,
                bc + (size_t)l * 2 * Dd, nullptr, uv, 2 * Dd, 0);
        scanA_kernel<<<SCAN_GRID, 256>>>(uv, theta + (size_t)l * NB, E);
        scanB_kernel<<<NCHAIN / 256, 256>>>(theta + (size_t)l * NB, E);
        scanC_kernel<<<SCAN_GRID, 256>>>(uv, theta + (size_t)l * NB, E, w);
        quant_kernel<<<ROWS, 256>>>(w, qa, sa);
        int flags = (l < Ll - 1) ? 1 : 0;
        gemm_s8_kernel<<<grid_DD, 256, GSMEM>>>(qa, sa,
                wq + (size_t)(8 + l) * WSLOT, sw + (size_t)(8 + l) * Dd,
                bh + (size_t)l * Dd, a, a, Dd, flags);
    }

    ln_quant_kernel<<<ROWS, 256>>>(a, lnf_g, lnf_b, qa, sa);
    gemm_s8_kernel<<<grid_DD, 256, GSMEM>>>(qa, sa,
            wq + (size_t)12 * WSLOT, sw + (size_t)12 * Dd, bo1, nullptr, w, Dd, 2);
    quant_kernel<<<ROWS, 256>>>(w, qa, sa);
    gemm_s8_kernel<<<grid_DV, 256, GSMEM>>>(qa, sa,
            wq + (size_t)13 * WSLOT, sw + (size_t)13 * Dd, bo2, nullptr,
            (float*)d_out, Vv, 0);
}